// round 8
// baseline (speedup 1.0000x reference)
#include <cuda_runtime.h>
#include <cuda_bf16.h>
#include <cstdint>

// Reference is mathematically the identity map (verified rel_err 2.9e-07):
// output (32,1,160000) == input (32,160000). Kernel = 20.48MB D2D copy.
//
// Model after R1-R7: wall = ~2us per-kernel fixed + reads paced at
// ~2.35 TB/s, invariant across LDG / TMA / CE / L2-pin / concurrent kernels.
// Last untested hypothesis: LDG MSHR pool and TMA bulk queue are paced
// INDEPENDENTLY when used concurrently inside one kernel.
//
// R8: 313 blocks x 64KB span. Per block: 32KB via TMA bulk G->S->G (thread 0,
// async) + 32KB via LDG/STG float4 MLP=8 (all 256 threads), concurrently.
// If paths are independent -> ~6.3us; if shared -> neutral (closes question).

#define TMA_CHUNK 32768
#define SPAN 65536
#define UNROLL 8

__global__ void __launch_bounds__(256) stft_copy_dual(
    const char* __restrict__ in, char* __restrict__ out, long long total)
{
    __shared__ alignas(128) char buf[TMA_CHUNK];
    __shared__ alignas(8) unsigned long long mbar;

    long long base = (long long)blockIdx.x * SPAN;
    if (base >= total) return;

    long long rem = total - base;
    unsigned tma_bytes = (unsigned)(rem < TMA_CHUNK ? rem : TMA_CHUNK);

    uint32_t s_buf = (uint32_t)__cvta_generic_to_shared(buf);
    uint32_t s_bar = (uint32_t)__cvta_generic_to_shared(&mbar);

    // --- thread 0: kick off async TMA read of first 32KB of the span ---
    if (threadIdx.x == 0) {
        asm volatile("mbarrier.init.shared.b64 [%0], %1;" :: "r"(s_bar), "r"(1));
        asm volatile("fence.proxy.async.shared::cta;" ::: "memory");
        asm volatile("mbarrier.arrive.expect_tx.shared.b64 _, [%0], %1;"
                     :: "r"(s_bar), "r"(tma_bytes));
        asm volatile(
            "cp.async.bulk.shared::cluster.global.mbarrier::complete_tx::bytes "
            "[%0], [%1], %2, [%3];"
            :: "r"(s_buf), "l"(in + base), "r"(tma_bytes), "r"(s_bar) : "memory");
    }

    // --- all threads: LDG/STG copy of second 32KB of the span (concurrent
    //     with the in-flight TMA read) ---
    long long ldg_base = base + TMA_CHUNK;
    if (ldg_base < total) {
        long long ldg_len = total - ldg_base;
        if (ldg_len > TMA_CHUNK) ldg_len = TMA_CHUNK;
        int n4 = (int)(ldg_len >> 4);          // float4 count (len % 16 == 0)
        const float4* src = (const float4*)(in + ldg_base);
        float4* dst = (float4*)(out + ldg_base);

        int idx = threadIdx.x;
        if (n4 == 256 * UNROLL) {
            float4 v[UNROLL];
#pragma unroll
            for (int k = 0; k < UNROLL; k++)
                v[k] = src[idx + k * 256];
#pragma unroll
            for (int k = 0; k < UNROLL; k++)
                dst[idx + k * 256] = v[k];
        } else {
#pragma unroll
            for (int k = 0; k < UNROLL; k++) {
                int i = idx + k * 256;
                if (i < n4) dst[i] = src[i];
            }
        }
    }

    // --- thread 0: wait for TMA read, bulk store back, drain ---
    if (threadIdx.x == 0) {
        uint32_t done = 0;
        while (!done) {
            asm volatile(
                "{\n\t.reg .pred p;\n\t"
                "mbarrier.try_wait.parity.acquire.cta.shared::cta.b64 p, [%1], %2, 0x989680;\n\t"
                "selp.b32 %0, 1, 0, p;\n\t}"
                : "=r"(done) : "r"(s_bar), "r"(0u) : "memory");
        }
        asm volatile("fence.proxy.async.shared::cta;" ::: "memory");
        asm volatile(
            "cp.async.bulk.global.shared::cta.bulk_group [%0], [%1], %2;"
            :: "l"(out + base), "r"(s_buf), "r"(tma_bytes) : "memory");
        asm volatile("cp.async.bulk.commit_group;" ::: "memory");
        asm volatile("cp.async.bulk.wait_group 0;" ::: "memory");
    }
}

extern "C" void kernel_launch(void* const* d_in, const int* in_sizes, int n_in,
                              void* d_out, int out_size) {
    const char* in = (const char*)d_in[0];
    char* out = (char*)d_out;
    long long total = (long long)out_size * sizeof(float);  // 20,480,000 bytes

    int blocks = (int)((total + SPAN - 1) / SPAN);          // 313
    stft_copy_dual<<<blocks, 256>>>(in, out, total);
}

// round 9
// speedup vs baseline: 1.2694x; 1.2694x over previous
#include <cuda_runtime.h>
#include <cuda_bf16.h>
#include <cstdint>

// Reference is mathematically the identity map (verified rel_err 2.9e-07):
// output (32,1,160000) == input (32,160000). Kernel = 20.48MB D2D copy.
//
// Mechanism sweep so far (all 8.7-9.0us, nothing saturated): LDG thin,
// LDG MLP=8 single wave, CE memcpy, TMA bulk, L2-pinned LDG, CE||SM fork,
// SM||SM fork, intra-kernel TMA+LDG dual path (10-11us, serialized).
// Model: ~4.4us mechanism-invariant in-kernel fixed cost + ~4.9 TB/s
// marginal aggregate R+W pacing, shared across all engines.
//
// R9: last untried path — non-coherent/texture reads (ld.global.nc,
// LDG.E.CONSTANT, separate L1 sector-queue discipline) + streaming
// evict-first stores (st.global.cs, reduces L2 thrash between the 21MB
// read stream and 21MB write stream). Shape: proven single-wave 625x256,
// front-batched MLP=8 float4. Exact fit, no tail (1,280,000 f4 = 625*2048).

#define UNROLL 8

__global__ void __launch_bounds__(256) stft_copy_nc(
    const float4* __restrict__ in, float4* __restrict__ out, int n4)
{
    int base = blockIdx.x * (256 * UNROLL) + threadIdx.x;

    if (base + 256 * (UNROLL - 1) < n4) {
        float4 v[UNROLL];
#pragma unroll
        for (int k = 0; k < UNROLL; k++) {
            const float4* p = in + base + k * 256;
            asm volatile(
                "ld.global.nc.L1::no_allocate.v4.f32 {%0,%1,%2,%3}, [%4];"
                : "=f"(v[k].x), "=f"(v[k].y), "=f"(v[k].z), "=f"(v[k].w)
                : "l"(p));
        }
#pragma unroll
        for (int k = 0; k < UNROLL; k++) {
            float4* p = out + base + k * 256;
            asm volatile(
                "st.global.cs.v4.f32 [%0], {%1,%2,%3,%4};"
                :: "l"(p), "f"(v[k].x), "f"(v[k].y), "f"(v[k].z), "f"(v[k].w)
                : "memory");
        }
    } else {
#pragma unroll
        for (int k = 0; k < UNROLL; k++) {
            int i = base + k * 256;
            if (i < n4) {
                float4 v = __ldg(in + i);
                float4* p = out + i;
                asm volatile(
                    "st.global.cs.v4.f32 [%0], {%1,%2,%3,%4};"
                    :: "l"(p), "f"(v.x), "f"(v.y), "f"(v.z), "f"(v.w)
                    : "memory");
            }
        }
    }
}

extern "C" void kernel_launch(void* const* d_in, const int* in_sizes, int n_in,
                              void* d_out, int out_size) {
    const float* in = (const float*)d_in[0];
    float* out = (float*)d_out;

    int n = out_size;                    // 5,120,000 floats
    int n4 = n >> 2;                     // 1,280,000 float4
    int per_block = 256 * UNROLL;        // 2048
    int blocks = (n4 + per_block - 1) / per_block;  // 625 — single wave

    stft_copy_nc<<<blocks, 256>>>((const float4*)in, (float4*)out, n4);

    int done = n4 << 2;
    if (done < n) {  // not reached for this fixed shape
        cudaMemcpyAsync(out + done, in + done, (size_t)(n - done) * sizeof(float),
                        cudaMemcpyDeviceToDevice, 0);
    }
}